// round 1
// baseline (speedup 1.0000x reference)
#include <cuda_runtime.h>
#include <math.h>
#include <stdint.h>

// Problem constants
#define B    128
#define S    400
#define T    50
#define H    512
#define E    128
#define V    50000
#define PADN 1000
#define J3H  1536      // 3*H
#define CB   1537      // 3*H + 1 (combined feature length)
#define VP   51000     // V + PADN

// ---- output layout (flattened tuple, float32) ----
// p_final (B,VP), p_gen (B,1), p_vocab (B,V), att_dist (B,S),
// decoder_h_states (B,T+1,H), h (B,H), new_previous_att (B,T+1,S)
#define PF_OFF  ((size_t)0)
#define PG_OFF  (PF_OFF + (size_t)B*VP)
#define PV_OFF  (PG_OFF + (size_t)B)
#define AD_OFF  (PV_OFF + (size_t)B*V)
#define DH_OFF  (AD_OFF + (size_t)B*S)
#define HH_OFF  (DH_OFF + (size_t)B*(T+1)*H)
#define NPA_OFF (HH_OFF + (size_t)B*H)

// ---- device scratch (static, no runtime allocation) ----
__device__ __align__(16) float g_Xt[640 * B];          // [k][b] (x rows 0..127, lh rows 128..639)
__device__ __align__(16) float g_gx[B * J3H];          // [b][j]
__device__ __align__(16) float g_gh[B * J3H];          // [b][j]
__device__ __align__(16) float g_h[B * H];
__device__ __align__(16) float g_hw[B * H];            // h * w_h
__device__ __align__(16) float g_hwd[B * H];           // h * w_d
__device__ __align__(16) float g_att_scores[B * S];
__device__ __align__(16) float g_ectx[B * H];
__device__ __align__(16) float g_dctx[B * H];
__device__ __align__(16) float g_comb[B * CB];         // [b][k] combined
__device__ __align__(16) float g_lh_t[E * B];          // logits_h transposed [e][b]
__device__ __align__(16) float g_logits[(size_t)B * V];
__device__ __align__(16) float g_sumexp[B];

// ============================================================
// K0: build Xt = [emb[token]; last_hidden] in [k][b] layout
// ============================================================
__global__ void k_build_xt(const int* __restrict__ tok,
                           const float* __restrict__ emb,
                           const float* __restrict__ lh) {
    int b = blockIdx.x;
    int t = tok[b];
    for (int k = threadIdx.x; k < 640; k += blockDim.x) {
        float v = (k < E) ? emb[(size_t)t * E + k] : lh[(size_t)b * H + (k - E)];
        g_Xt[k * B + b] = v;
    }
}

// ============================================================
// K1: generic C[b][j] = sum_k W[j][k] * Xt[k][b]
// grid (J/128, 16), 256 threads. Each thread: 1 j, 4 b.
// ============================================================
__global__ void k_gemm_jb(const float* __restrict__ W, int K,
                          const float* __restrict__ Xt,
                          float* __restrict__ C, int ldC) {
    int jl    = threadIdx.x & 127;
    int half  = threadIdx.x >> 7;
    int j     = blockIdx.x * 128 + jl;
    int bbase = blockIdx.y * 8 + half * 4;
    const float4* Wr = reinterpret_cast<const float4*>(W + (size_t)j * K);
    float a0 = 0.f, a1 = 0.f, a2 = 0.f, a3 = 0.f;
    int K4 = K >> 2;
    for (int k4 = 0; k4 < K4; k4++) {
        float4 w = Wr[k4];
        const float* xb = Xt + (size_t)(k4 * 4) * B + bbase;
        float4 x0 = *reinterpret_cast<const float4*>(xb);
        float4 x1 = *reinterpret_cast<const float4*>(xb + B);
        float4 x2 = *reinterpret_cast<const float4*>(xb + 2 * B);
        float4 x3 = *reinterpret_cast<const float4*>(xb + 3 * B);
        a0 += w.x * x0.x + w.y * x1.x + w.z * x2.x + w.w * x3.x;
        a1 += w.x * x0.y + w.y * x1.y + w.z * x2.y + w.w * x3.y;
        a2 += w.x * x0.z + w.y * x1.z + w.z * x2.z + w.w * x3.z;
        a3 += w.x * x0.w + w.y * x1.w + w.z * x2.w + w.w * x3.w;
    }
    C[(size_t)(bbase + 0) * ldC + j] = a0;
    C[(size_t)(bbase + 1) * ldC + j] = a1;
    C[(size_t)(bbase + 2) * ldC + j] = a2;
    C[(size_t)(bbase + 3) * ldC + j] = a3;
}

// ============================================================
// K2: GRU gates -> h, h*w_h, h*w_d; write h outputs
// ============================================================
__global__ void k_gates(const float* __restrict__ lh,
                        const float* __restrict__ b_ih,
                        const float* __restrict__ b_hh,
                        const float* __restrict__ w_h,
                        const float* __restrict__ w_d,
                        float* __restrict__ out) {
    int b = blockIdx.x, i = threadIdx.x;  // 512 threads
    float gx0 = g_gx[(size_t)b * J3H + i]           + b_ih[i];
    float gh0 = g_gh[(size_t)b * J3H + i]           + b_hh[i];
    float gx1 = g_gx[(size_t)b * J3H + H + i]       + b_ih[H + i];
    float gh1 = g_gh[(size_t)b * J3H + H + i]       + b_hh[H + i];
    float gx2 = g_gx[(size_t)b * J3H + 2 * H + i]   + b_ih[2 * H + i];
    float gh2 = g_gh[(size_t)b * J3H + 2 * H + i]   + b_hh[2 * H + i];
    float r = 1.f / (1.f + expf(-(gx0 + gh0)));
    float z = 1.f / (1.f + expf(-(gx1 + gh1)));
    float n = tanhf(gx2 + r * gh2);
    float hl = lh[(size_t)b * H + i];
    float h = (1.f - z) * n + z * hl;
    g_h[(size_t)b * H + i]   = h;
    g_hw[(size_t)b * H + i]  = h * w_h[i];
    g_hwd[(size_t)b * H + i] = h * w_d[i];
    out[HH_OFF + (size_t)b * H + i] = h;
    out[DH_OFF + ((size_t)b * (T + 1) + T) * H + i] = h;
}

// ============================================================
// K3: att_scores[b,s] = sum_h hw[b,h]*enc[b,s,h]  (warp per (b,s))
// ============================================================
__global__ void k_attsc(const float* __restrict__ enc) {
    int wg   = blockIdx.x * 8 + (threadIdx.x >> 5);
    int lane = threadIdx.x & 31;
    int b = wg / S, s = wg % S;
    const float4* e4 = reinterpret_cast<const float4*>(enc + ((size_t)b * S + s) * H);
    const float4* h4 = reinterpret_cast<const float4*>(g_hw + (size_t)b * H);
    float acc = 0.f;
#pragma unroll
    for (int q = 0; q < 4; q++) {
        int idx = q * 32 + lane;
        float4 e = e4[idx], hv = h4[idx];
        acc += e.x * hv.x + e.y * hv.y + e.z * hv.z + e.w * hv.w;
    }
    for (int o = 16; o; o >>= 1) acc += __shfl_xor_sync(0xffffffffu, acc, o);
    if (!lane) g_att_scores[b * S + s] = acc;
}

// ============================================================
// K4: temporal attention + att_dist + new_previous_att
// ============================================================
__global__ void k_temporal(const float* __restrict__ pa, float* __restrict__ out) {
    __shared__ float red[16];
    int b = blockIdx.x, s = threadIdx.x;  // 512 threads
    float tmp = 0.f;
    if (s < S) {
        float denom = 0.f;
        for (int t = 0; t < T; t++) {
            float v = pa[((size_t)b * T + t) * S + s];
            out[NPA_OFF + ((size_t)b * (T + 1) + t) * S + s] = v;
            denom += expf(v);
        }
        float asc = g_att_scores[b * S + s];
        out[NPA_OFF + ((size_t)b * (T + 1) + T) * S + s] = asc;
        tmp = expf(asc) / denom;
    }
    float v = tmp;
    for (int o = 16; o; o >>= 1) v += __shfl_xor_sync(0xffffffffu, v, o);
    if ((threadIdx.x & 31) == 0) red[threadIdx.x >> 5] = v;
    __syncthreads();
    if (threadIdx.x < 16) {
        float r = red[threadIdx.x];
        for (int o = 8; o; o >>= 1) r += __shfl_xor_sync(0xffffu, r, o);
        if (!threadIdx.x) red[0] = r;
    }
    __syncthreads();
    if (s < S) out[AD_OFF + (size_t)b * S + s] = tmp / red[0];
}

// ============================================================
// K5: encoder_context[b,h] = sum_s att_dist[b,s]*enc[b,s,h]
// ============================================================
__global__ void k_ectx(const float* __restrict__ enc, const float* __restrict__ out_ro) {
    __shared__ float att[S];
    int b = blockIdx.x, h = threadIdx.x;  // 512 threads
    if (h < S) att[h] = out_ro[AD_OFF + (size_t)b * S + h];
    __syncthreads();
    float a0 = 0, a1 = 0, a2 = 0, a3 = 0, a4 = 0, a5 = 0, a6 = 0, a7 = 0;
    const float* eb = enc + (size_t)b * S * H + h;
    for (int s = 0; s < S; s += 8) {
        a0 += att[s + 0] * eb[(size_t)(s + 0) * H];
        a1 += att[s + 1] * eb[(size_t)(s + 1) * H];
        a2 += att[s + 2] * eb[(size_t)(s + 2) * H];
        a3 += att[s + 3] * eb[(size_t)(s + 3) * H];
        a4 += att[s + 4] * eb[(size_t)(s + 4) * H];
        a5 += att[s + 5] * eb[(size_t)(s + 5) * H];
        a6 += att[s + 6] * eb[(size_t)(s + 6) * H];
        a7 += att[s + 7] * eb[(size_t)(s + 7) * H];
    }
    g_ectx[(size_t)b * H + h] = ((a0 + a1) + (a2 + a3)) + ((a4 + a5) + (a6 + a7));
}

// ============================================================
// K6: decoder attention + decoder_context + decoder_h_states copy
// dynamic smem: T*H + 128 floats
// ============================================================
__global__ void k_dec(const float* __restrict__ pds, float* __restrict__ out) {
    extern __shared__ float sm[];
    float* pd = sm;               // [T*H]
    float* sc = sm + T * H;       // [64]
    float* at = sc + 64;          // [64]
    int b = blockIdx.x, tid = threadIdx.x;  // 512 threads
    for (int idx = tid; idx < T * H; idx += 512) {
        float v = pds[(size_t)b * T * H + idx];
        pd[idx] = v;
        int t = idx >> 9, hh = idx & 511;
        out[DH_OFF + ((size_t)b * (T + 1) + t) * H + hh] = v;
    }
    __syncthreads();
    int w = tid >> 5, lane = tid & 31;
    for (int t = w; t < T; t += 16) {
        float acc = 0.f;
#pragma unroll
        for (int q = 0; q < 16; q++)
            acc += g_hwd[(size_t)b * H + q * 32 + lane] * pd[t * H + q * 32 + lane];
        for (int o = 16; o; o >>= 1) acc += __shfl_xor_sync(0xffffffffu, acc, o);
        if (!lane) sc[t] = acc;
    }
    __syncthreads();
    if (tid < 32) {
        float s1 = (tid < T) ? sc[tid] : -1e30f;
        float s2 = (tid + 32 < T) ? sc[tid + 32] : -1e30f;
        float m = fmaxf(s1, s2);
        for (int o = 16; o; o >>= 1) m = fmaxf(m, __shfl_xor_sync(0xffffffffu, m, o));
        float e1 = (tid < T) ? expf(s1 - m) : 0.f;
        float e2 = (tid + 32 < T) ? expf(s2 - m) : 0.f;
        float sum = e1 + e2;
        for (int o = 16; o; o >>= 1) sum += __shfl_xor_sync(0xffffffffu, sum, o);
        if (tid < T) at[tid] = e1 / sum;
        if (tid + 32 < T) at[tid + 32] = e2 / sum;
    }
    __syncthreads();
    float acc = 0.f;
    for (int t = 0; t < T; t++) acc += at[t] * pd[t * H + tid];
    g_dctx[(size_t)b * H + tid] = acc;
}

// ============================================================
// K7: combined = [h, ectx, dctx, control]
// ============================================================
__global__ void k_comb(const float* __restrict__ ctrl) {
    int b = blockIdx.x;
    for (int k = threadIdx.x; k < CB; k += blockDim.x) {
        float v;
        if (k < H)           v = g_h[(size_t)b * H + k];
        else if (k < 2 * H)  v = g_ectx[(size_t)b * H + k - H];
        else if (k < 3 * H)  v = g_dctx[(size_t)b * H + k - 2 * H];
        else                 v = ctrl[b];
        g_comb[(size_t)b * CB + k] = v;
    }
}

// ============================================================
// K8: logits_h[e][b] = combined[b] . outh_W[e] + outh_b[e]
// grid (16 e-blocks of 8, 4 b-blocks of 32), 256 threads
// ============================================================
__global__ void k_outh(const float* __restrict__ Wo, const float* __restrict__ bo) {
    __shared__ float Ws[8 * 128];
    __shared__ float Cs[32 * 129];
    int el = threadIdx.x >> 5, bl = threadIdx.x & 31;
    int e = blockIdx.x * 8 + el, bb = blockIdx.y * 32 + bl;
    float acc = 0.f;
    for (int kc = 0; kc < 1536; kc += 128) {
        __syncthreads();
        for (int idx = threadIdx.x; idx < 1024; idx += 256) {
            int ee = idx >> 7, k = idx & 127;
            Ws[idx] = Wo[(size_t)(blockIdx.x * 8 + ee) * CB + kc + k];
        }
        for (int idx = threadIdx.x; idx < 4096; idx += 256) {
            int b2 = idx >> 7, k = idx & 127;
            Cs[b2 * 129 + k] = g_comb[(size_t)(blockIdx.y * 32 + b2) * CB + kc + k];
        }
        __syncthreads();
#pragma unroll 8
        for (int k = 0; k < 128; k++)
            acc += Ws[el * 128 + k] * Cs[bl * 129 + k];
    }
    acc += Wo[(size_t)e * CB + 1536] * g_comb[(size_t)bb * CB + 1536];
    g_lh_t[e * B + bb] = acc + bo[e];
}

// ============================================================
// K9: p_gen[b] = sigmoid(combined[b] . gen_W + gen_b)
// ============================================================
__global__ void k_pgen(const float* __restrict__ gw, const float* __restrict__ gb,
                       float* __restrict__ out) {
    int b = blockIdx.x * 8 + (threadIdx.x >> 5);
    int lane = threadIdx.x & 31;
    float acc = 0.f;
    for (int k = lane; k < CB; k += 32) acc += g_comb[(size_t)b * CB + k] * gw[k];
    for (int o = 16; o; o >>= 1) acc += __shfl_xor_sync(0xffffffffu, acc, o);
    if (!lane) out[PG_OFF + b] = 1.f / (1.f + expf(-(acc + gb[0])));
}

// ============================================================
// K10: logits_v = logits_h @ outv_W.T + outv_b
// grid (ceil(V/128)), 512 threads, dynamic smem 128*129 + 128*128 floats
// ============================================================
__global__ void k_outv(const float* __restrict__ Wv, const float* __restrict__ bv) {
    extern __shared__ float sm[];
    float* Ws = sm;               // [k*129 + vl]
    float* Xs = sm + 128 * 129;   // [k*128 + b]
    int vbase = blockIdx.x * 128;
    int tid = threadIdx.x;
    for (int idx = tid; idx < 128 * 128; idx += 512) {
        int vl = idx >> 7, k = idx & 127;
        int v = vbase + vl;
        Ws[k * 129 + vl] = (v < V) ? Wv[(size_t)v * E + k] : 0.f;
    }
    for (int idx = tid; idx < 128 * 128; idx += 512) {
        Xs[idx] = g_lh_t[idx];
    }
    __syncthreads();
    int vg = tid >> 5, bg = tid & 31;
    int vl0 = vg * 8, b0 = bg * 4;
    float acc[4][8];
#pragma unroll
    for (int i = 0; i < 4; i++)
#pragma unroll
        for (int u = 0; u < 8; u++) acc[i][u] = 0.f;
#pragma unroll 4
    for (int k = 0; k < 128; k++) {
        float w0 = Ws[k * 129 + vl0 + 0];
        float w1 = Ws[k * 129 + vl0 + 1];
        float w2 = Ws[k * 129 + vl0 + 2];
        float w3 = Ws[k * 129 + vl0 + 3];
        float w4 = Ws[k * 129 + vl0 + 4];
        float w5 = Ws[k * 129 + vl0 + 5];
        float w6 = Ws[k * 129 + vl0 + 6];
        float w7 = Ws[k * 129 + vl0 + 7];
        float4 xv = *reinterpret_cast<const float4*>(&Xs[k * 128 + b0]);
        acc[0][0] += xv.x * w0; acc[0][1] += xv.x * w1; acc[0][2] += xv.x * w2; acc[0][3] += xv.x * w3;
        acc[0][4] += xv.x * w4; acc[0][5] += xv.x * w5; acc[0][6] += xv.x * w6; acc[0][7] += xv.x * w7;
        acc[1][0] += xv.y * w0; acc[1][1] += xv.y * w1; acc[1][2] += xv.y * w2; acc[1][3] += xv.y * w3;
        acc[1][4] += xv.y * w4; acc[1][5] += xv.y * w5; acc[1][6] += xv.y * w6; acc[1][7] += xv.y * w7;
        acc[2][0] += xv.z * w0; acc[2][1] += xv.z * w1; acc[2][2] += xv.z * w2; acc[2][3] += xv.z * w3;
        acc[2][4] += xv.z * w4; acc[2][5] += xv.z * w5; acc[2][6] += xv.z * w6; acc[2][7] += xv.z * w7;
        acc[3][0] += xv.w * w0; acc[3][1] += xv.w * w1; acc[3][2] += xv.w * w2; acc[3][3] += xv.w * w3;
        acc[3][4] += xv.w * w4; acc[3][5] += xv.w * w5; acc[3][6] += xv.w * w6; acc[3][7] += xv.w * w7;
    }
#pragma unroll
    for (int i = 0; i < 4; i++) {
        int b = b0 + i;
        float* dst = g_logits + (size_t)b * V + vbase + vl0;
        if (vbase + 128 <= V) {
#pragma unroll
            for (int u = 0; u < 8; u++) acc[i][u] += bv[vbase + vl0 + u];
            *reinterpret_cast<float4*>(dst)     = make_float4(acc[i][0], acc[i][1], acc[i][2], acc[i][3]);
            *reinterpret_cast<float4*>(dst + 4) = make_float4(acc[i][4], acc[i][5], acc[i][6], acc[i][7]);
        } else {
#pragma unroll
            for (int u = 0; u < 8; u++) {
                int v = vbase + vl0 + u;
                if (v < V) dst[u] = acc[i][u] + bv[v];
            }
        }
    }
}

// ============================================================
// K11: sumexp over vocab per row (softmax denominator; no max
// subtraction needed — logits are O(±5), mathematically identical)
// ============================================================
__global__ void k_sumexp() {
    __shared__ float red[16];
    int b = blockIdx.x;
    float acc = 0.f;
    for (int v = threadIdx.x; v < V; v += 512)
        acc += expf(g_logits[(size_t)b * V + v]);
    for (int o = 16; o; o >>= 1) acc += __shfl_xor_sync(0xffffffffu, acc, o);
    if ((threadIdx.x & 31) == 0) red[threadIdx.x >> 5] = acc;
    __syncthreads();
    if (threadIdx.x < 16) {
        float r = red[threadIdx.x];
        for (int o = 8; o; o >>= 1) r += __shfl_xor_sync(0xffffu, r, o);
        if (!threadIdx.x) g_sumexp[b] = r;
    }
}

// ============================================================
// K12: p_vocab, p_final (vocab part + zero pad)
// ============================================================
__global__ void k_pfinal(float* __restrict__ out) {
    int b = blockIdx.y;
    int v = blockIdx.x * 256 + threadIdx.x;
    float pg = out[PG_OFF + b];
    if (v < V) {
        float p = expf(g_logits[(size_t)b * V + v]) / g_sumexp[b];
        out[PV_OFF + (size_t)b * V + v] = p;
        out[PF_OFF + (size_t)b * VP + v] = p * pg;
    } else if (v < VP) {
        out[PF_OFF + (size_t)b * VP + v] = 0.f;
    }
}

// ============================================================
// K13: pointer scatter: p_final[b, idx] += (1-p_gen)*att_dist
// ============================================================
__global__ void k_scatter(const int* __restrict__ fiv, float* __restrict__ out) {
    int b = blockIdx.x, s = threadIdx.x;
    if (s < S) {
        float pg = out[PG_OFF + b];
        float val = (1.f - pg) * out[AD_OFF + (size_t)b * S + s];
        int idx = fiv[(size_t)b * S + s];
        atomicAdd(&out[PF_OFF + (size_t)b * VP + idx], val);
    }
}

// ============================================================
// launch
// ============================================================
extern "C" void kernel_launch(void* const* d_in, const int* in_sizes, int n_in,
                              void* d_out, int out_size) {
    const int*   tok   = (const int*)  d_in[0];
    const float* pds   = (const float*)d_in[1];   // prev_decoder_h_states
    const float* lh    = (const float*)d_in[2];   // last_hidden
    const float* enc   = (const float*)d_in[3];   // encoder_states
    const int*   fiv   = (const int*)  d_in[4];   // full_input_var
    const float* pa    = (const float*)d_in[5];   // previous_att
    const float* ctrl  = (const float*)d_in[6];   // control_var
    const float* emb   = (const float*)d_in[7];
    const float* W_ih  = (const float*)d_in[8];
    const float* W_hh  = (const float*)d_in[9];
    const float* b_ih  = (const float*)d_in[10];
    const float* b_hh  = (const float*)d_in[11];
    const float* w_h   = (const float*)d_in[12];
    const float* w_d   = (const float*)d_in[13];
    const float* gen_W = (const float*)d_in[14];
    const float* gen_b = (const float*)d_in[15];
    const float* outh_W= (const float*)d_in[16];
    const float* outh_b= (const float*)d_in[17];
    const float* outv_W= (const float*)d_in[18];
    const float* outv_b= (const float*)d_in[19];
    float* out = (float*)d_out;

    const int DEC_SMEM  = (T * H + 128) * sizeof(float);        // ~102.9 KB
    const int OUTV_SMEM = (128 * 129 + 128 * 128) * sizeof(float); // ~131.6 KB
    cudaFuncSetAttribute(k_dec,  cudaFuncAttributeMaxDynamicSharedMemorySize, DEC_SMEM);
    cudaFuncSetAttribute(k_outv, cudaFuncAttributeMaxDynamicSharedMemorySize, OUTV_SMEM);

    float* d_gx; cudaGetSymbolAddress((void**)&d_gx, g_gx);
    float* d_gh; cudaGetSymbolAddress((void**)&d_gh, g_gh);
    float* d_xt; cudaGetSymbolAddress((void**)&d_xt, g_Xt);

    // GRU
    k_build_xt<<<B, 256>>>(tok, emb, lh);
    k_gemm_jb<<<dim3(J3H / 128, 16), 256>>>(W_ih, E, d_xt, d_gx, J3H);
    k_gemm_jb<<<dim3(J3H / 128, 16), 256>>>(W_hh, H, d_xt + E * B, d_gh, J3H);
    k_gates<<<B, 512>>>(lh, b_ih, b_hh, w_h, w_d, out);
    // temporal encoder attention
    k_attsc<<<(B * S) / 8, 256>>>(enc);
    k_temporal<<<B, 512>>>(pa, out);
    k_ectx<<<B, 512>>>(enc, out);
    // decoder attention
    k_dec<<<B, 512, DEC_SMEM>>>(pds, out);
    // output head
    k_comb<<<B, 512>>>(ctrl);
    k_outh<<<dim3(16, 4), 256>>>(outh_W, outh_b);
    k_pgen<<<16, 256>>>(gen_W, gen_b, out);
    k_outv<<<(V + 127) / 128, 512, OUTV_SMEM>>>(outv_W, outv_b);
    // softmax + final distribution
    k_sumexp<<<B, 512>>>();
    k_pfinal<<<dim3((VP + 255) / 256, B), 256>>>(out);
    k_scatter<<<B, 512>>>(fiv, out);
}

// round 3
// speedup vs baseline: 1.4668x; 1.4668x over previous
#include <cuda_runtime.h>
#include <cuda_bf16.h>
#include <math.h>
#include <stdint.h>

// Problem constants
#define B    128
#define S    400
#define T    50
#define H    512
#define E    128
#define V    50000
#define PADN 1000
#define J3H  1536
#define CB   1537
#define VP   51000

// ---- output layout (flattened tuple, float32) ----
#define PF_OFF  ((size_t)0)
#define PG_OFF  (PF_OFF + (size_t)B*VP)
#define PV_OFF  (PG_OFF + (size_t)B)
#define AD_OFF  (PV_OFF + (size_t)B*V)
#define DH_OFF  (AD_OFF + (size_t)B*S)
#define HH_OFF  (DH_OFF + (size_t)B*(T+1)*H)
#define NPA_OFF (HH_OFF + (size_t)B*H)

// ---- device scratch ----
__device__ __align__(16) float g_Xt[640 * B];          // [k][b]
__device__ __align__(16) float g_gx[B * J3H];
__device__ __align__(16) float g_gh[B * J3H];
__device__ __align__(16) float g_h[B * H];
__device__ __align__(16) float g_hw[B * H];
__device__ __align__(16) float g_hwd[B * H];
__device__ __align__(16) float g_att_scores[B * S];
__device__ __align__(16) float g_ectx[B * H];
__device__ __align__(16) float g_dctx[B * H];
__device__ __align__(16) float g_comb[B * CB];
__device__ __align__(16) float g_lhb[B * E];           // logits_h [b][e]
__device__ __align__(16) float g_logits[(size_t)B * V];// holds exp(logits)
__device__ __align__(16) float g_sumexp[B];

// ============================================================
// K0: build Xt = [emb[token]; last_hidden] in [k][b] layout
// ============================================================
__global__ void k_build_xt(const int* __restrict__ tok,
                           const float* __restrict__ emb,
                           const float* __restrict__ lh) {
    int b = blockIdx.x;
    int t = tok[b];
    for (int k = threadIdx.x; k < 640; k += blockDim.x) {
        float v = (k < E) ? emb[(size_t)t * E + k] : lh[(size_t)b * H + (k - E)];
        g_Xt[k * B + b] = v;
    }
}

// ============================================================
// K1: fused GRU GEMMs, smem-tiled.
// gridDim = (12, 8, 2): z=0 -> gx = W_ih @ x ; z=1 -> gh = W_hh @ lh
// ============================================================
__global__ void __launch_bounds__(256) k_grugemm(const float* __restrict__ Wih,
                                                 const float* __restrict__ Whh) {
    const float* W = blockIdx.z ? Whh : Wih;
    float* Cdst    = blockIdx.z ? g_gh : g_gx;
    const float* X = g_Xt + (blockIdx.z ? E * B : 0);
    int K = blockIdx.z ? H : E;

    __shared__ float Ws[128][33];
    __shared__ float Xs[32][17];
    int tid = threadIdx.x;
    int j0 = blockIdx.x * 128, b0 = blockIdx.y * 16;
    int tj = tid & 31, tb = tid >> 5;
    float acc[4][2];
#pragma unroll
    for (int q = 0; q < 4; q++) { acc[q][0] = 0.f; acc[q][1] = 0.f; }

    for (int kc = 0; kc < K; kc += 32) {
        __syncthreads();
#pragma unroll
        for (int q = 0; q < 4; q++) {
            int idx = tid + q * 256;
            int r = idx >> 3, c = (idx & 7) * 4;
            float4 w = *reinterpret_cast<const float4*>(W + (size_t)(j0 + r) * K + kc + c);
            Ws[r][c] = w.x; Ws[r][c + 1] = w.y; Ws[r][c + 2] = w.z; Ws[r][c + 3] = w.w;
        }
#pragma unroll
        for (int q = 0; q < 2; q++) {
            int e = tid + q * 256;
            int k = e >> 4, bb = e & 15;
            Xs[k][bb] = X[(size_t)(kc + k) * B + b0 + bb];
        }
        __syncthreads();
#pragma unroll
        for (int k = 0; k < 32; k++) {
            float x0 = Xs[k][tb * 2], x1 = Xs[k][tb * 2 + 1];
#pragma unroll
            for (int q = 0; q < 4; q++) {
                float w = Ws[tj + q * 32][k];
                acc[q][0] += w * x0;
                acc[q][1] += w * x1;
            }
        }
    }
#pragma unroll
    for (int q = 0; q < 4; q++) {
        int j = j0 + tj + q * 32;
        Cdst[(size_t)(b0 + tb * 2) * J3H + j]     = acc[q][0];
        Cdst[(size_t)(b0 + tb * 2 + 1) * J3H + j] = acc[q][1];
    }
}

// ============================================================
// K2: GRU gates; also zeros g_ectx. 512 blocks x 128 threads.
// ============================================================
__global__ void k_gates(const float* __restrict__ lh,
                        const float* __restrict__ b_ih,
                        const float* __restrict__ b_hh,
                        const float* __restrict__ w_h,
                        const float* __restrict__ w_d,
                        float* __restrict__ out) {
    int b = blockIdx.x >> 2;
    int i = ((blockIdx.x & 3) << 7) + threadIdx.x;
    float gx0 = g_gx[(size_t)b * J3H + i]         + b_ih[i];
    float gh0 = g_gh[(size_t)b * J3H + i]         + b_hh[i];
    float gx1 = g_gx[(size_t)b * J3H + H + i]     + b_ih[H + i];
    float gh1 = g_gh[(size_t)b * J3H + H + i]     + b_hh[H + i];
    float gx2 = g_gx[(size_t)b * J3H + 2 * H + i] + b_ih[2 * H + i];
    float gh2 = g_gh[(size_t)b * J3H + 2 * H + i] + b_hh[2 * H + i];
    float r = 1.f / (1.f + expf(-(gx0 + gh0)));
    float z = 1.f / (1.f + expf(-(gx1 + gh1)));
    float n = tanhf(gx2 + r * gh2);
    float hl = lh[(size_t)b * H + i];
    float h = (1.f - z) * n + z * hl;
    g_h[(size_t)b * H + i]   = h;
    g_hw[(size_t)b * H + i]  = h * w_h[i];
    g_hwd[(size_t)b * H + i] = h * w_d[i];
    g_ectx[(size_t)b * H + i] = 0.f;
    out[HH_OFF + (size_t)b * H + i] = h;
    out[DH_OFF + ((size_t)b * (T + 1) + T) * H + i] = h;
}

// ============================================================
// K3: att_scores[b,s] = sum_h hw[b,h]*enc[b,s,h]
// ============================================================
__global__ void k_attsc(const float* __restrict__ enc) {
    int wg   = blockIdx.x * 8 + (threadIdx.x >> 5);
    int lane = threadIdx.x & 31;
    int b = wg / S, s = wg % S;
    const float4* e4 = reinterpret_cast<const float4*>(enc + ((size_t)b * S + s) * H);
    const float4* h4 = reinterpret_cast<const float4*>(g_hw + (size_t)b * H);
    float acc = 0.f;
#pragma unroll
    for (int q = 0; q < 4; q++) {
        int idx = q * 32 + lane;
        float4 e = e4[idx], hv = h4[idx];
        acc += e.x * hv.x + e.y * hv.y + e.z * hv.z + e.w * hv.w;
    }
    for (int o = 16; o; o >>= 1) acc += __shfl_xor_sync(0xffffffffu, acc, o);
    if (!lane) g_att_scores[b * S + s] = acc;
}

// ============================================================
// K4: temporal attention + att_dist + new_previous_att
// ============================================================
__global__ void k_temporal(const float* __restrict__ pa, float* __restrict__ out) {
    __shared__ float red[16];
    int b = blockIdx.x, s = threadIdx.x;
    float tmp = 0.f;
    if (s < S) {
        float denom = 0.f;
        for (int t = 0; t < T; t++) {
            float v = pa[((size_t)b * T + t) * S + s];
            out[NPA_OFF + ((size_t)b * (T + 1) + t) * S + s] = v;
            denom += expf(v);
        }
        float asc = g_att_scores[b * S + s];
        out[NPA_OFF + ((size_t)b * (T + 1) + T) * S + s] = asc;
        tmp = expf(asc) / denom;
    }
    float v = tmp;
    for (int o = 16; o; o >>= 1) v += __shfl_xor_sync(0xffffffffu, v, o);
    if ((threadIdx.x & 31) == 0) red[threadIdx.x >> 5] = v;
    __syncthreads();
    if (threadIdx.x < 16) {
        float r = red[threadIdx.x];
        for (int o = 8; o; o >>= 1) r += __shfl_xor_sync(0xffffu, r, o);
        if (!threadIdx.x) red[0] = r;
    }
    __syncthreads();
    if (s < S) out[AD_OFF + (size_t)b * S + s] = tmp / red[0];
}

// ============================================================
// K5: encoder_context partial: grid (5, B), 80 s-rows per block
// ============================================================
__global__ void k_ectx(const float* __restrict__ enc, const float* __restrict__ out_ro) {
    __shared__ float att[80];
    int sy = blockIdx.x, b = blockIdx.y;
    int s0 = sy * 80;
    int h = threadIdx.x;
    if (h < 80) att[h] = out_ro[AD_OFF + (size_t)b * S + s0 + h];
    __syncthreads();
    float a0 = 0, a1 = 0, a2 = 0, a3 = 0, a4 = 0, a5 = 0, a6 = 0, a7 = 0;
    const float* eb = enc + ((size_t)b * S + s0) * H + h;
    for (int s = 0; s < 80; s += 8) {
        a0 += att[s + 0] * eb[(size_t)(s + 0) * H];
        a1 += att[s + 1] * eb[(size_t)(s + 1) * H];
        a2 += att[s + 2] * eb[(size_t)(s + 2) * H];
        a3 += att[s + 3] * eb[(size_t)(s + 3) * H];
        a4 += att[s + 4] * eb[(size_t)(s + 4) * H];
        a5 += att[s + 5] * eb[(size_t)(s + 5) * H];
        a6 += att[s + 6] * eb[(size_t)(s + 6) * H];
        a7 += att[s + 7] * eb[(size_t)(s + 7) * H];
    }
    atomicAdd(&g_ectx[(size_t)b * H + h], ((a0 + a1) + (a2 + a3)) + ((a4 + a5) + (a6 + a7)));
}

// ============================================================
// K6: decoder attention + decoder_context + decoder_h_states copy
// ============================================================
__global__ void k_dec(const float* __restrict__ pds, float* __restrict__ out) {
    extern __shared__ float sm[];
    float* pd = sm;
    float* sc = sm + T * H;
    float* at = sc + 64;
    int b = blockIdx.x, tid = threadIdx.x;
    for (int idx = tid; idx < T * H; idx += 512) {
        float v = pds[(size_t)b * T * H + idx];
        pd[idx] = v;
        int t = idx >> 9, hh = idx & 511;
        out[DH_OFF + ((size_t)b * (T + 1) + t) * H + hh] = v;
    }
    __syncthreads();
    int w = tid >> 5, lane = tid & 31;
    for (int t = w; t < T; t += 16) {
        float acc = 0.f;
#pragma unroll
        for (int q = 0; q < 16; q++)
            acc += g_hwd[(size_t)b * H + q * 32 + lane] * pd[t * H + q * 32 + lane];
        for (int o = 16; o; o >>= 1) acc += __shfl_xor_sync(0xffffffffu, acc, o);
        if (!lane) sc[t] = acc;
    }
    __syncthreads();
    if (tid < 32) {
        float s1 = (tid < T) ? sc[tid] : -1e30f;
        float s2 = (tid + 32 < T) ? sc[tid + 32] : -1e30f;
        float m = fmaxf(s1, s2);
        for (int o = 16; o; o >>= 1) m = fmaxf(m, __shfl_xor_sync(0xffffffffu, m, o));
        float e1 = (tid < T) ? expf(s1 - m) : 0.f;
        float e2 = (tid + 32 < T) ? expf(s2 - m) : 0.f;
        float sum = e1 + e2;
        for (int o = 16; o; o >>= 1) sum += __shfl_xor_sync(0xffffffffu, sum, o);
        if (tid < T) at[tid] = e1 / sum;
        if (tid + 32 < T) at[tid + 32] = e2 / sum;
    }
    __syncthreads();
    float acc = 0.f;
    for (int t = 0; t < T; t++) acc += at[t] * pd[t * H + tid];
    g_dctx[(size_t)b * H + tid] = acc;
}

// ============================================================
// K7: combined = [h, ectx, dctx, control]; zero g_sumexp
// ============================================================
__global__ void k_comb(const float* __restrict__ ctrl) {
    int b = blockIdx.x;
    if (threadIdx.x == 0) g_sumexp[b] = 0.f;
    for (int k = threadIdx.x; k < CB; k += blockDim.x) {
        float v;
        if (k < H)          v = g_h[(size_t)b * H + k];
        else if (k < 2 * H) v = g_ectx[(size_t)b * H + k - H];
        else if (k < 3 * H) v = g_dctx[(size_t)b * H + k - 2 * H];
        else                v = ctrl[b];
        g_comb[(size_t)b * CB + k] = v;
    }
}

// ============================================================
// K8: logits_h[b][e] = combined[b] . outh_W[e] + outh_b[e]
// ============================================================
__global__ void k_outh(const float* __restrict__ Wo, const float* __restrict__ bo) {
    __shared__ float Ws[8 * 128];
    __shared__ float Cs[32 * 129];
    int el = threadIdx.x >> 5, bl = threadIdx.x & 31;
    int e = blockIdx.x * 8 + el, bb = blockIdx.y * 32 + bl;
    float acc = 0.f;
    for (int kc = 0; kc < 1536; kc += 128) {
        __syncthreads();
        for (int idx = threadIdx.x; idx < 1024; idx += 256) {
            int ee = idx >> 7, k = idx & 127;
            Ws[idx] = Wo[(size_t)(blockIdx.x * 8 + ee) * CB + kc + k];
        }
        for (int idx = threadIdx.x; idx < 4096; idx += 256) {
            int b2 = idx >> 7, k = idx & 127;
            Cs[b2 * 129 + k] = g_comb[(size_t)(blockIdx.y * 32 + b2) * CB + kc + k];
        }
        __syncthreads();
#pragma unroll 8
        for (int k = 0; k < 128; k++)
            acc += Ws[el * 128 + k] * Cs[bl * 129 + k];
    }
    acc += Wo[(size_t)e * CB + 1536] * g_comb[(size_t)bb * CB + 1536];
    g_lhb[(size_t)bb * E + e] = acc + bo[e];
}

// ============================================================
// K9: p_gen
// ============================================================
__global__ void k_pgen(const float* __restrict__ gw, const float* __restrict__ gb,
                       float* __restrict__ out) {
    int b = blockIdx.x * 8 + (threadIdx.x >> 5);
    int lane = threadIdx.x & 31;
    float acc = 0.f;
    for (int k = lane; k < CB; k += 32) acc += g_comb[(size_t)b * CB + k] * gw[k];
    for (int o = 16; o; o >>= 1) acc += __shfl_xor_sync(0xffffffffu, acc, o);
    if (!lane) out[PG_OFF + b] = 1.f / (1.f + expf(-(acc + gb[0])));
}

// ============================================================
// K10: vocab GEMM via mma.sync bf16 3-term split (hi*hi + hi*lo + lo*hi)
// + fused bias + exp + row-sum atomics.
// D[b][v] tile 128x128 per block. 256 threads = 8 warps (2m x 4n).
// ============================================================
#define TSTR  132                      // bf16 elements per row (padded)
#define TILEB (128 * TSTR * 2)         // 33792 bytes per bf16 tile
#define AHI_O 0
#define ALO_O (TILEB)
#define BHI_O (2 * TILEB)
#define BLO_O (3 * TILEB)
#define OUTV_DSMEM (4 * TILEB)

__device__ __forceinline__ void split2(float a, float b, uint32_t& hv, uint32_t& lv) {
    __nv_bfloat162 hi = __float22bfloat162_rn(make_float2(a, b));
    float ra = a - __bfloat162float(hi.x);
    float rb = b - __bfloat162float(hi.y);
    __nv_bfloat162 lo = __float22bfloat162_rn(make_float2(ra, rb));
    hv = *reinterpret_cast<uint32_t*>(&hi);
    lv = *reinterpret_cast<uint32_t*>(&lo);
}
__device__ __forceinline__ void mma16816(float* c, const uint32_t* a, const uint32_t* b) {
    asm volatile(
        "mma.sync.aligned.m16n8k16.row.col.f32.bf16.bf16.f32 "
        "{%0,%1,%2,%3}, {%4,%5,%6,%7}, {%8,%9}, {%0,%1,%2,%3};"
        : "+f"(c[0]), "+f"(c[1]), "+f"(c[2]), "+f"(c[3])
        : "r"(a[0]), "r"(a[1]), "r"(a[2]), "r"(a[3]), "r"(b[0]), "r"(b[1]));
}

__global__ void __launch_bounds__(256, 1)
k_outv_mma(const float* __restrict__ Wv, const float* __restrict__ bv) {
    extern __shared__ char smc[];
    __shared__ float s_bv[128];
    int tid = threadIdx.x;
    int vbase = blockIdx.x * 128;

    if (tid < 128) s_bv[tid] = (vbase + tid < V) ? bv[vbase + tid] : 0.f;

    // ---- convert W tile and X into hi/lo bf16 tiles (row-major, stride TSTR) ----
#pragma unroll 4
    for (int q = 0; q < 16; q++) {
        int idx = tid + q * 256;       // 4096 float4 slots
        int r = idx >> 5;
        int c = (idx & 31) * 4;
        float4 w = make_float4(0.f, 0.f, 0.f, 0.f);
        if (vbase + r < V) w = *reinterpret_cast<const float4*>(Wv + (size_t)(vbase + r) * E + c);
        uint32_t h0, l0, h1, l1;
        split2(w.x, w.y, h0, l0);
        split2(w.z, w.w, h1, l1);
        size_t off = (size_t)(r * TSTR + c) * 2;
        *reinterpret_cast<uint2*>(smc + BHI_O + off) = make_uint2(h0, h1);
        *reinterpret_cast<uint2*>(smc + BLO_O + off) = make_uint2(l0, l1);
        float4 x = *reinterpret_cast<const float4*>(g_lhb + (size_t)r * E + c);
        split2(x.x, x.y, h0, l0);
        split2(x.z, x.w, h1, l1);
        *reinterpret_cast<uint2*>(smc + AHI_O + off) = make_uint2(h0, h1);
        *reinterpret_cast<uint2*>(smc + ALO_O + off) = make_uint2(l0, l1);
    }
    __syncthreads();

    int wid = tid >> 5, lane = tid & 31;
    int wm = wid >> 2, wn = wid & 3;      // warp tile: m 64 rows, n 32 cols
    int g = lane >> 2, t = lane & 3;

    float acc[4][4][4];
#pragma unroll
    for (int mi = 0; mi < 4; mi++)
#pragma unroll
        for (int ni = 0; ni < 4; ni++)
#pragma unroll
            for (int r = 0; r < 4; r++) acc[mi][ni][r] = 0.f;

#pragma unroll
    for (int term = 0; term < 3; term++) {
        int aoff = (term == 2) ? ALO_O : AHI_O;
        int boff = (term == 1) ? BLO_O : BHI_O;
        for (int ks = 0; ks < 8; ks++) {
            int kb = ks * 16;
            uint32_t af[4][4], bf[4][2];
#pragma unroll
            for (int mi = 0; mi < 4; mi++) {
                int row = wm * 64 + mi * 16 + g;
                size_t o = (size_t)aoff + (size_t)(row * TSTR + kb + 2 * t) * 2;
                af[mi][0] = *reinterpret_cast<const uint32_t*>(smc + o);
                af[mi][1] = *reinterpret_cast<const uint32_t*>(smc + o + 8 * TSTR * 2);
                af[mi][2] = *reinterpret_cast<const uint32_t*>(smc + o + 16);
                af[mi][3] = *reinterpret_cast<const uint32_t*>(smc + o + 8 * TSTR * 2 + 16);
            }
#pragma unroll
            for (int ni = 0; ni < 4; ni++) {
                int row = wn * 32 + ni * 8 + g;
                size_t o = (size_t)boff + (size_t)(row * TSTR + kb + 2 * t) * 2;
                bf[ni][0] = *reinterpret_cast<const uint32_t*>(smc + o);
                bf[ni][1] = *reinterpret_cast<const uint32_t*>(smc + o + 16);
            }
#pragma unroll
            for (int mi = 0; mi < 4; mi++)
#pragma unroll
                for (int ni = 0; ni < 4; ni++)
                    mma16816(acc[mi][ni], af[mi], bf[ni]);
        }
    }
    __syncthreads();   // all smem reads done; reuse as stage

    // ---- epilogue: bias + exp, stage in smem ----
    float* stage = reinterpret_cast<float*>(smc);   // [128][TSTR]
#pragma unroll
    for (int mi = 0; mi < 4; mi++) {
        int r0 = wm * 64 + mi * 16 + g;
#pragma unroll
        for (int ni = 0; ni < 4; ni++) {
            int n0 = wn * 32 + ni * 8 + 2 * t;
            bool v0 = (vbase + n0 < V), v1 = (vbase + n0 + 1 < V);
            float e00 = v0 ? expf(acc[mi][ni][0] + s_bv[n0])     : 0.f;
            float e01 = v1 ? expf(acc[mi][ni][1] + s_bv[n0 + 1]) : 0.f;
            float e10 = v0 ? expf(acc[mi][ni][2] + s_bv[n0])     : 0.f;
            float e11 = v1 ? expf(acc[mi][ni][3] + s_bv[n0 + 1]) : 0.f;
            stage[r0 * TSTR + n0]           = e00;
            stage[r0 * TSTR + n0 + 1]       = e01;
            stage[(r0 + 8) * TSTR + n0]     = e10;
            stage[(r0 + 8) * TSTR + n0 + 1] = e11;
        }
    }
    __syncthreads();

    // ---- row sums -> atomicAdd, coalesced store of exp(logits) ----
    if (tid < 128) {
        float lsum = 0.f;
        for (int c = 0; c < 128; c++) lsum += stage[tid * TSTR + c];
        atomicAdd(&g_sumexp[tid], lsum);
    }
    for (int idx = tid; idx < 128 * 128; idx += 256) {
        int b = idx >> 7, c = idx & 127;
        if (vbase + c < V) g_logits[(size_t)b * V + vbase + c] = stage[b * TSTR + c];
    }
}

// ============================================================
// K11: p_vocab, p_final (vocab part + zero pad)
// ============================================================
__global__ void k_pfinal(float* __restrict__ out) {
    int b = blockIdx.y;
    int v = blockIdx.x * 256 + threadIdx.x;
    float pg = out[PG_OFF + b];
    if (v < V) {
        float p = g_logits[(size_t)b * V + v] / g_sumexp[b];
        out[PV_OFF + (size_t)b * V + v] = p;
        out[PF_OFF + (size_t)b * VP + v] = p * pg;
    } else if (v < VP) {
        out[PF_OFF + (size_t)b * VP + v] = 0.f;
    }
}

// ============================================================
// K12: pointer scatter
// ============================================================
__global__ void k_scatter(const int* __restrict__ fiv, float* __restrict__ out) {
    int b = blockIdx.x, s = threadIdx.x;
    if (s < S) {
        float pg = out[PG_OFF + b];
        float val = (1.f - pg) * out[AD_OFF + (size_t)b * S + s];
        int idx = fiv[(size_t)b * S + s];
        atomicAdd(&out[PF_OFF + (size_t)b * VP + idx], val);
    }
}

// ============================================================
// launch
// ============================================================
extern "C" void kernel_launch(void* const* d_in, const int* in_sizes, int n_in,
                              void* d_out, int out_size) {
    const int*   tok    = (const int*)  d_in[0];
    const float* pds    = (const float*)d_in[1];
    const float* lh     = (const float*)d_in[2];
    const float* enc    = (const float*)d_in[3];
    const int*   fiv    = (const int*)  d_in[4];
    const float* pa     = (const float*)d_in[5];
    const float* ctrl   = (const float*)d_in[6];
    const float* emb    = (const float*)d_in[7];
    const float* W_ih   = (const float*)d_in[8];
    const float* W_hh   = (const float*)d_in[9];
    const float* b_ih   = (const float*)d_in[10];
    const float* b_hh   = (const float*)d_in[11];
    const float* w_h    = (const float*)d_in[12];
    const float* w_d    = (const float*)d_in[13];
    const float* gen_W  = (const float*)d_in[14];
    const float* gen_b  = (const float*)d_in[15];
    const float* outh_W = (const float*)d_in[16];
    const float* outh_b = (const float*)d_in[17];
    const float* outv_W = (const float*)d_in[18];
    const float* outv_b = (const float*)d_in[19];
    float* out = (float*)d_out;

    const int DEC_SMEM = (T * H + 128) * sizeof(float);
    cudaFuncSetAttribute(k_dec, cudaFuncAttributeMaxDynamicSharedMemorySize, DEC_SMEM);
    cudaFuncSetAttribute(k_outv_mma, cudaFuncAttributeMaxDynamicSharedMemorySize, OUTV_DSMEM);

    k_build_xt<<<B, 256>>>(tok, emb, lh);
    k_grugemm<<<dim3(J3H / 128, B / 16, 2), 256>>>(W_ih, W_hh);
    k_gates<<<4 * B, 128>>>(lh, b_ih, b_hh, w_h, w_d, out);
    k_attsc<<<(B * S) / 8, 256>>>(enc);
    k_temporal<<<B, 512>>>(pa, out);
    k_ectx<<<dim3(5, B), 512>>>(enc, out);
    k_dec<<<B, 512, DEC_SMEM>>>(pds, out);
    k_comb<<<B, 512>>>(ctrl);
    k_outh<<<dim3(16, 4), 256>>>(outh_W, outh_b);
    k_pgen<<<16, 256>>>(gen_W, gen_b, out);
    k_outv_mma<<<(V + 127) / 128, 256, OUTV_DSMEM>>>(outv_W, outv_b);
    k_pfinal<<<dim3((VP + 255) / 256, B), 256>>>(out);
    k_scatter<<<B, 512>>>(fiv, out);
}

// round 4
// speedup vs baseline: 1.5645x; 1.0666x over previous
#include <cuda_runtime.h>
#include <cuda_bf16.h>
#include <math.h>
#include <stdint.h>

// Problem constants
#define B    128
#define S    400
#define T    50
#define H    512
#define E    128
#define V    50000
#define PADN 1000
#define J3H  1536
#define CB   1537
#define VP   51000

// ---- output layout (flattened tuple, float32) ----
#define PF_OFF  ((size_t)0)
#define PG_OFF  (PF_OFF + (size_t)B*VP)
#define PV_OFF  (PG_OFF + (size_t)B)
#define AD_OFF  (PV_OFF + (size_t)B*V)
#define DH_OFF  (AD_OFF + (size_t)B*S)
#define HH_OFF  (DH_OFF + (size_t)B*(T+1)*H)
#define NPA_OFF (HH_OFF + (size_t)B*H)

// ---- device scratch ----
__device__ __align__(16) float g_gx[B * J3H];
__device__ __align__(16) float g_gh[B * J3H];
__device__ __align__(16) float g_h[B * H];
__device__ __align__(16) float g_hw[B * H];
__device__ __align__(16) float g_hwd[B * H];
__device__ __align__(16) float g_att_scores[B * S];
__device__ __align__(16) float g_ectx[B * H];
__device__ __align__(16) float g_dctx[B * H];
__device__ __align__(16) float g_lhb[B * E];           // logits_h [b][e]
__device__ __align__(16) float g_logits[(size_t)B * V];// holds exp(logits)
__device__ __align__(16) float g_sumexp[B];

// ============================================================
// K1: fused GRU GEMMs, smem-tiled, X gathered directly from emb/lh.
// gridDim = (12, 8, 2): z=0 -> gx = W_ih @ x ; z=1 -> gh = W_hh @ lh
// ============================================================
__global__ void __launch_bounds__(256) k_grugemm(const float* __restrict__ Wih,
                                                 const float* __restrict__ Whh,
                                                 const int* __restrict__ tok,
                                                 const float* __restrict__ emb,
                                                 const float* __restrict__ lh) {
    int z = blockIdx.z;
    const float* W = z ? Whh : Wih;
    float* Cdst    = z ? g_gh : g_gx;
    int K = z ? H : E;

    __shared__ float Ws[128][33];
    __shared__ float Xs[32][17];
    __shared__ int stok[16];
    int tid = threadIdx.x;
    int j0 = blockIdx.x * 128, b0 = blockIdx.y * 16;
    if (tid < 16) stok[tid] = tok[b0 + tid];
    int tj = tid & 31, tb = tid >> 5;
    float acc[4][2];
#pragma unroll
    for (int q = 0; q < 4; q++) { acc[q][0] = 0.f; acc[q][1] = 0.f; }

    for (int kc = 0; kc < K; kc += 32) {
        __syncthreads();
#pragma unroll
        for (int q = 0; q < 4; q++) {
            int idx = tid + q * 256;
            int r = idx >> 3, c = (idx & 7) * 4;
            float4 w = *reinterpret_cast<const float4*>(W + (size_t)(j0 + r) * K + kc + c);
            Ws[r][c] = w.x; Ws[r][c + 1] = w.y; Ws[r][c + 2] = w.z; Ws[r][c + 3] = w.w;
        }
#pragma unroll
        for (int q = 0; q < 2; q++) {
            int e = tid + q * 256;
            int k = e >> 4, bb = e & 15;
            float xv;
            if (z == 0) xv = emb[(size_t)stok[bb] * E + kc + k];
            else        xv = lh[(size_t)(b0 + bb) * H + kc + k];
            Xs[k][bb] = xv;
        }
        __syncthreads();
#pragma unroll
        for (int k = 0; k < 32; k++) {
            float x0 = Xs[k][tb * 2], x1 = Xs[k][tb * 2 + 1];
#pragma unroll
            for (int q = 0; q < 4; q++) {
                float w = Ws[tj + q * 32][k];
                acc[q][0] += w * x0;
                acc[q][1] += w * x1;
            }
        }
    }
#pragma unroll
    for (int q = 0; q < 4; q++) {
        int j = j0 + tj + q * 32;
        Cdst[(size_t)(b0 + tb * 2) * J3H + j]     = acc[q][0];
        Cdst[(size_t)(b0 + tb * 2 + 1) * J3H + j] = acc[q][1];
    }
}

// ============================================================
// K2: GRU gates; also zeros g_ectx.
// ============================================================
__global__ void k_gates(const float* __restrict__ lh,
                        const float* __restrict__ b_ih,
                        const float* __restrict__ b_hh,
                        const float* __restrict__ w_h,
                        const float* __restrict__ w_d,
                        float* __restrict__ out) {
    int b = blockIdx.x >> 2;
    int i = ((blockIdx.x & 3) << 7) + threadIdx.x;
    float gx0 = g_gx[(size_t)b * J3H + i]         + b_ih[i];
    float gh0 = g_gh[(size_t)b * J3H + i]         + b_hh[i];
    float gx1 = g_gx[(size_t)b * J3H + H + i]     + b_ih[H + i];
    float gh1 = g_gh[(size_t)b * J3H + H + i]     + b_hh[H + i];
    float gx2 = g_gx[(size_t)b * J3H + 2 * H + i] + b_ih[2 * H + i];
    float gh2 = g_gh[(size_t)b * J3H + 2 * H + i] + b_hh[2 * H + i];
    float r = 1.f / (1.f + __expf(-(gx0 + gh0)));
    float z = 1.f / (1.f + __expf(-(gx1 + gh1)));
    float n = tanhf(gx2 + r * gh2);
    float hl = lh[(size_t)b * H + i];
    float h = (1.f - z) * n + z * hl;
    g_h[(size_t)b * H + i]   = h;
    g_hw[(size_t)b * H + i]  = h * w_h[i];
    g_hwd[(size_t)b * H + i] = h * w_d[i];
    g_ectx[(size_t)b * H + i] = 0.f;
    out[HH_OFF + (size_t)b * H + i] = h;
    out[DH_OFF + ((size_t)b * (T + 1) + T) * H + i] = h;
}

// ============================================================
// K3: att_scores[b,s] = sum_h hw[b,h]*enc[b,s,h]
// ============================================================
__global__ void k_attsc(const float* __restrict__ enc) {
    int wg   = blockIdx.x * 8 + (threadIdx.x >> 5);
    int lane = threadIdx.x & 31;
    int b = wg / S, s = wg % S;
    const float4* e4 = reinterpret_cast<const float4*>(enc + ((size_t)b * S + s) * H);
    const float4* h4 = reinterpret_cast<const float4*>(g_hw + (size_t)b * H);
    float acc = 0.f;
#pragma unroll
    for (int q = 0; q < 4; q++) {
        int idx = q * 32 + lane;
        float4 e = e4[idx], hv = h4[idx];
        acc += e.x * hv.x + e.y * hv.y + e.z * hv.z + e.w * hv.w;
    }
    for (int o = 16; o; o >>= 1) acc += __shfl_xor_sync(0xffffffffu, acc, o);
    if (!lane) g_att_scores[b * S + s] = acc;
}

// ============================================================
// K4: temporal attention + att_dist + new_previous_att
// ============================================================
__global__ void k_temporal(const float* __restrict__ pa, float* __restrict__ out) {
    __shared__ float red[16];
    int b = blockIdx.x, s = threadIdx.x;
    float tmp = 0.f;
    if (s < S) {
        float denom = 0.f;
        for (int t = 0; t < T; t++) {
            float v = pa[((size_t)b * T + t) * S + s];
            out[NPA_OFF + ((size_t)b * (T + 1) + t) * S + s] = v;
            denom += __expf(v);
        }
        float asc = g_att_scores[b * S + s];
        out[NPA_OFF + ((size_t)b * (T + 1) + T) * S + s] = asc;
        tmp = __expf(asc) / denom;
    }
    float v = tmp;
    for (int o = 16; o; o >>= 1) v += __shfl_xor_sync(0xffffffffu, v, o);
    if ((threadIdx.x & 31) == 0) red[threadIdx.x >> 5] = v;
    __syncthreads();
    if (threadIdx.x < 16) {
        float r = red[threadIdx.x];
        for (int o = 8; o; o >>= 1) r += __shfl_xor_sync(0xffffu, r, o);
        if (!threadIdx.x) red[0] = r;
    }
    __syncthreads();
    if (s < S) out[AD_OFF + (size_t)b * S + s] = tmp / red[0];
}

// ============================================================
// K5: encoder_context partial: grid (5, B), 80 s-rows per block
// ============================================================
__global__ void k_ectx(const float* __restrict__ enc, const float* __restrict__ out_ro) {
    __shared__ float att[80];
    int sy = blockIdx.x, b = blockIdx.y;
    int s0 = sy * 80;
    int h = threadIdx.x;
    if (h < 80) att[h] = out_ro[AD_OFF + (size_t)b * S + s0 + h];
    __syncthreads();
    float a0 = 0, a1 = 0, a2 = 0, a3 = 0, a4 = 0, a5 = 0, a6 = 0, a7 = 0;
    const float* eb = enc + ((size_t)b * S + s0) * H + h;
    for (int s = 0; s < 80; s += 8) {
        a0 += att[s + 0] * eb[(size_t)(s + 0) * H];
        a1 += att[s + 1] * eb[(size_t)(s + 1) * H];
        a2 += att[s + 2] * eb[(size_t)(s + 2) * H];
        a3 += att[s + 3] * eb[(size_t)(s + 3) * H];
        a4 += att[s + 4] * eb[(size_t)(s + 4) * H];
        a5 += att[s + 5] * eb[(size_t)(s + 5) * H];
        a6 += att[s + 6] * eb[(size_t)(s + 6) * H];
        a7 += att[s + 7] * eb[(size_t)(s + 7) * H];
    }
    atomicAdd(&g_ectx[(size_t)b * H + h], ((a0 + a1) + (a2 + a3)) + ((a4 + a5) + (a6 + a7)));
}

// ============================================================
// K6: decoder attention + decoder_context + decoder_h_states copy
// ============================================================
__global__ void k_dec(const float* __restrict__ pds, float* __restrict__ out) {
    extern __shared__ float sm[];
    float* pd = sm;
    float* sc = sm + T * H;
    float* at = sc + 64;
    int b = blockIdx.x, tid = threadIdx.x;
    for (int idx = tid; idx < T * H; idx += 512) {
        float v = pds[(size_t)b * T * H + idx];
        pd[idx] = v;
        int t = idx >> 9, hh = idx & 511;
        out[DH_OFF + ((size_t)b * (T + 1) + t) * H + hh] = v;
    }
    __syncthreads();
    int w = tid >> 5, lane = tid & 31;
    for (int t = w; t < T; t += 16) {
        float acc = 0.f;
#pragma unroll
        for (int q = 0; q < 16; q++)
            acc += g_hwd[(size_t)b * H + q * 32 + lane] * pd[t * H + q * 32 + lane];
        for (int o = 16; o; o >>= 1) acc += __shfl_xor_sync(0xffffffffu, acc, o);
        if (!lane) sc[t] = acc;
    }
    __syncthreads();
    if (tid < 32) {
        float s1 = (tid < T) ? sc[tid] : -1e30f;
        float s2 = (tid + 32 < T) ? sc[tid + 32] : -1e30f;
        float m = fmaxf(s1, s2);
        for (int o = 16; o; o >>= 1) m = fmaxf(m, __shfl_xor_sync(0xffffffffu, m, o));
        float e1 = (tid < T) ? __expf(s1 - m) : 0.f;
        float e2 = (tid + 32 < T) ? __expf(s2 - m) : 0.f;
        float sum = e1 + e2;
        for (int o = 16; o; o >>= 1) sum += __shfl_xor_sync(0xffffffffu, sum, o);
        if (tid < T) at[tid] = e1 / sum;
        if (tid + 32 < T) at[tid + 32] = e2 / sum;
    }
    __syncthreads();
    float acc = 0.f;
    for (int t = 0; t < T; t++) acc += at[t] * pd[t * H + tid];
    g_dctx[(size_t)b * H + tid] = acc;
}

// ============================================================
// K8: logits_h[b][e] = combined[b] . outh_W[e] + outh_b[e]
// combined gathered on the fly from g_h/g_ectx/g_dctx/ctrl
// ============================================================
__global__ void k_outh(const float* __restrict__ Wo, const float* __restrict__ bo,
                       const float* __restrict__ ctrl) {
    __shared__ float Ws[8 * 128];
    __shared__ float Cs[32 * 129];
    int el = threadIdx.x >> 5, bl = threadIdx.x & 31;
    int e = blockIdx.x * 8 + el, bb = blockIdx.y * 32 + bl;
    float acc = 0.f;
    for (int kc = 0; kc < 1536; kc += 128) {
        __syncthreads();
        for (int idx = threadIdx.x; idx < 1024; idx += 256) {
            int ee = idx >> 7, k = idx & 127;
            Ws[idx] = Wo[(size_t)(blockIdx.x * 8 + ee) * CB + kc + k];
        }
        const float* src = (kc < 512) ? (g_h + kc)
                         : (kc < 1024) ? (g_ectx + kc - 512)
                                       : (g_dctx + kc - 1024);
        for (int idx = threadIdx.x; idx < 4096; idx += 256) {
            int b2 = idx >> 7, k = idx & 127;
            Cs[b2 * 129 + k] = src[(size_t)(blockIdx.y * 32 + b2) * H + k];
        }
        __syncthreads();
#pragma unroll 8
        for (int k = 0; k < 128; k++)
            acc += Ws[el * 128 + k] * Cs[bl * 129 + k];
    }
    acc += Wo[(size_t)e * CB + 1536] * ctrl[bb];
    g_lhb[(size_t)bb * E + e] = acc + bo[e];
}

// ============================================================
// K9: p_gen (gathers combined on the fly); also zeros g_sumexp
// ============================================================
__global__ void k_pgen(const float* __restrict__ gw, const float* __restrict__ gb,
                       const float* __restrict__ ctrl, float* __restrict__ out) {
    int b = blockIdx.x * 8 + (threadIdx.x >> 5);
    int lane = threadIdx.x & 31;
    float acc = 0.f;
    for (int k = lane; k < H; k += 32) {
        acc += g_h[(size_t)b * H + k]    * gw[k];
        acc += g_ectx[(size_t)b * H + k] * gw[H + k];
        acc += g_dctx[(size_t)b * H + k] * gw[2 * H + k];
    }
    if (!lane) acc += ctrl[b] * gw[1536];
    for (int o = 16; o; o >>= 1) acc += __shfl_xor_sync(0xffffffffu, acc, o);
    if (!lane) {
        out[PG_OFF + b] = 1.f / (1.f + __expf(-(acc + gb[0])));
        g_sumexp[b] = 0.f;
    }
}

// ============================================================
// K10: vocab GEMM via mma.sync bf16 3-term split + bias + exp + row sums
// 128x128 tile per block, 512 threads = 16 warps (4m x 4n)
// ============================================================
#define TSTR  132
#define TILEB (128 * TSTR * 2)
#define AHI_O 0
#define ALO_O (TILEB)
#define BHI_O (2 * TILEB)
#define BLO_O (3 * TILEB)
#define OUTV_DSMEM (4 * TILEB)

__device__ __forceinline__ void split2(float a, float b, uint32_t& hv, uint32_t& lv) {
    __nv_bfloat162 hi = __float22bfloat162_rn(make_float2(a, b));
    float ra = a - __bfloat162float(hi.x);
    float rb = b - __bfloat162float(hi.y);
    __nv_bfloat162 lo = __float22bfloat162_rn(make_float2(ra, rb));
    hv = *reinterpret_cast<uint32_t*>(&hi);
    lv = *reinterpret_cast<uint32_t*>(&lo);
}
__device__ __forceinline__ void mma16816(float* c, const uint32_t* a, const uint32_t* b) {
    asm volatile(
        "mma.sync.aligned.m16n8k16.row.col.f32.bf16.bf16.f32 "
        "{%0,%1,%2,%3}, {%4,%5,%6,%7}, {%8,%9}, {%0,%1,%2,%3};"
        : "+f"(c[0]), "+f"(c[1]), "+f"(c[2]), "+f"(c[3])
        : "r"(a[0]), "r"(a[1]), "r"(a[2]), "r"(a[3]), "r"(b[0]), "r"(b[1]));
}

__global__ void __launch_bounds__(512, 1)
k_outv_mma(const float* __restrict__ Wv, const float* __restrict__ bv) {
    extern __shared__ char smc[];
    __shared__ float s_bv[128];
    int tid = threadIdx.x;
    int vbase = blockIdx.x * 128;

    if (tid < 128) s_bv[tid] = (vbase + tid < V) ? bv[vbase + tid] : 0.f;

    // ---- convert W tile and X into hi/lo bf16 tiles ----
#pragma unroll
    for (int q = 0; q < 8; q++) {
        int idx = tid + q * 512;       // 4096 float4 slots
        int r = idx >> 5;
        int c = (idx & 31) * 4;
        float4 w = make_float4(0.f, 0.f, 0.f, 0.f);
        if (vbase + r < V) w = *reinterpret_cast<const float4*>(Wv + (size_t)(vbase + r) * E + c);
        uint32_t h0, l0, h1, l1;
        split2(w.x, w.y, h0, l0);
        split2(w.z, w.w, h1, l1);
        size_t off = (size_t)(r * TSTR + c) * 2;
        *reinterpret_cast<uint2*>(smc + BHI_O + off) = make_uint2(h0, h1);
        *reinterpret_cast<uint2*>(smc + BLO_O + off) = make_uint2(l0, l1);
        float4 x = *reinterpret_cast<const float4*>(g_lhb + (size_t)r * E + c);
        split2(x.x, x.y, h0, l0);
        split2(x.z, x.w, h1, l1);
        *reinterpret_cast<uint2*>(smc + AHI_O + off) = make_uint2(h0, h1);
        *reinterpret_cast<uint2*>(smc + ALO_O + off) = make_uint2(l0, l1);
    }
    __syncthreads();

    int wid = tid >> 5, lane = tid & 31;
    int wm = wid >> 2, wn = wid & 3;      // warp tile: 32 rows x 32 cols
    int g = lane >> 2, t = lane & 3;

    float acc[2][4][4];
#pragma unroll
    for (int mi = 0; mi < 2; mi++)
#pragma unroll
        for (int ni = 0; ni < 4; ni++)
#pragma unroll
            for (int r = 0; r < 4; r++) acc[mi][ni][r] = 0.f;

#pragma unroll
    for (int term = 0; term < 3; term++) {
        int aoff = (term == 2) ? ALO_O : AHI_O;
        int boff = (term == 1) ? BLO_O : BHI_O;
#pragma unroll
        for (int ks = 0; ks < 8; ks++) {
            int kb = ks * 16;
            uint32_t af[2][4], bf[4][2];
#pragma unroll
            for (int mi = 0; mi < 2; mi++) {
                int row = wm * 32 + mi * 16 + g;
                size_t o = (size_t)aoff + (size_t)(row * TSTR + kb + 2 * t) * 2;
                af[mi][0] = *reinterpret_cast<const uint32_t*>(smc + o);
                af[mi][1] = *reinterpret_cast<const uint32_t*>(smc + o + 8 * TSTR * 2);
                af[mi][2] = *reinterpret_cast<const uint32_t*>(smc + o + 16);
                af[mi][3] = *reinterpret_cast<const uint32_t*>(smc + o + 8 * TSTR * 2 + 16);
            }
#pragma unroll
            for (int ni = 0; ni < 4; ni++) {
                int row = wn * 32 + ni * 8 + g;
                size_t o = (size_t)boff + (size_t)(row * TSTR + kb + 2 * t) * 2;
                bf[ni][0] = *reinterpret_cast<const uint32_t*>(smc + o);
                bf[ni][1] = *reinterpret_cast<const uint32_t*>(smc + o + 16);
            }
#pragma unroll
            for (int mi = 0; mi < 2; mi++)
#pragma unroll
                for (int ni = 0; ni < 4; ni++)
                    mma16816(acc[mi][ni], af[mi], bf[ni]);
        }
    }
    __syncthreads();

    // ---- epilogue: bias + exp, stage in smem ----
    float* stage = reinterpret_cast<float*>(smc);   // [128][TSTR]
#pragma unroll
    for (int mi = 0; mi < 2; mi++) {
        int r0 = wm * 32 + mi * 16 + g;
#pragma unroll
        for (int ni = 0; ni < 4; ni++) {
            int n0 = wn * 32 + ni * 8 + 2 * t;
            bool v0 = (vbase + n0 < V), v1 = (vbase + n0 + 1 < V);
            float e00 = v0 ? __expf(acc[mi][ni][0] + s_bv[n0])     : 0.f;
            float e01 = v1 ? __expf(acc[mi][ni][1] + s_bv[n0 + 1]) : 0.f;
            float e10 = v0 ? __expf(acc[mi][ni][2] + s_bv[n0])     : 0.f;
            float e11 = v1 ? __expf(acc[mi][ni][3] + s_bv[n0 + 1]) : 0.f;
            stage[r0 * TSTR + n0]           = e00;
            stage[r0 * TSTR + n0 + 1]       = e01;
            stage[(r0 + 8) * TSTR + n0]     = e10;
            stage[(r0 + 8) * TSTR + n0 + 1] = e11;
        }
    }
    __syncthreads();

    // ---- row sums + coalesced store of exp(logits) ----
    if (tid < 256) {
        int row = tid >> 1, half = tid & 1;
        float lsum = 0.f;
        for (int c = half * 64; c < half * 64 + 64; c++) lsum += stage[row * TSTR + c];
        atomicAdd(&g_sumexp[row], lsum);
    }
    for (int idx = tid; idx < 128 * 128; idx += 512) {
        int b = idx >> 7, c = idx & 127;
        if (vbase + c < V) g_logits[(size_t)b * V + vbase + c] = stage[b * TSTR + c];
    }
}

// ============================================================
// K11: p_vocab, p_final (vectorized float4)
// ============================================================
__global__ void k_pfinal(float* __restrict__ out) {
    int b = blockIdx.y;
    int v = (blockIdx.x * 256 + threadIdx.x) * 4;
    if (v >= VP) return;
    float pg = out[PG_OFF + b];
    if (v < V) {
        float4 L = *reinterpret_cast<const float4*>(g_logits + (size_t)b * V + v);
        float inv = __fdividef(1.f, g_sumexp[b]);
        float4 p = make_float4(L.x * inv, L.y * inv, L.z * inv, L.w * inv);
        *reinterpret_cast<float4*>(out + PV_OFF + (size_t)b * V + v) = p;
        *reinterpret_cast<float4*>(out + PF_OFF + (size_t)b * VP + v) =
            make_float4(p.x * pg, p.y * pg, p.z * pg, p.w * pg);
    } else {
        *reinterpret_cast<float4*>(out + PF_OFF + (size_t)b * VP + v) =
            make_float4(0.f, 0.f, 0.f, 0.f);
    }
}

// ============================================================
// K12: pointer scatter
// ============================================================
__global__ void k_scatter(const int* __restrict__ fiv, float* __restrict__ out) {
    int b = blockIdx.x, s = threadIdx.x;
    if (s < S) {
        float pg = out[PG_OFF + b];
        float val = (1.f - pg) * out[AD_OFF + (size_t)b * S + s];
        int idx = fiv[(size_t)b * S + s];
        atomicAdd(&out[PF_OFF + (size_t)b * VP + idx], val);
    }
}

// ============================================================
// launch — fork/join capture-safe stream overlap
// ============================================================
extern "C" void kernel_launch(void* const* d_in, const int* in_sizes, int n_in,
                              void* d_out, int out_size) {
    const int*   tok    = (const int*)  d_in[0];
    const float* pds    = (const float*)d_in[1];
    const float* lh     = (const float*)d_in[2];
    const float* enc    = (const float*)d_in[3];
    const int*   fiv    = (const int*)  d_in[4];
    const float* pa     = (const float*)d_in[5];
    const float* ctrl   = (const float*)d_in[6];
    const float* emb    = (const float*)d_in[7];
    const float* W_ih   = (const float*)d_in[8];
    const float* W_hh   = (const float*)d_in[9];
    const float* b_ih   = (const float*)d_in[10];
    const float* b_hh   = (const float*)d_in[11];
    const float* w_h    = (const float*)d_in[12];
    const float* w_d    = (const float*)d_in[13];
    const float* gen_W  = (const float*)d_in[14];
    const float* gen_b  = (const float*)d_in[15];
    const float* outh_W = (const float*)d_in[16];
    const float* outh_b = (const float*)d_in[17];
    const float* outv_W = (const float*)d_in[18];
    const float* outv_b = (const float*)d_in[19];
    float* out = (float*)d_out;

    const int DEC_SMEM = (T * H + 128) * sizeof(float);
    cudaFuncSetAttribute(k_dec, cudaFuncAttributeMaxDynamicSharedMemorySize, DEC_SMEM);
    cudaFuncSetAttribute(k_outv_mma, cudaFuncAttributeMaxDynamicSharedMemorySize, OUTV_DSMEM);

    cudaStream_t s1;
    cudaStreamCreateWithFlags(&s1, cudaStreamNonBlocking);
    cudaEvent_t evGates, evDec, evEctx, evPgen;
    cudaEventCreateWithFlags(&evGates, cudaEventDisableTiming);
    cudaEventCreateWithFlags(&evDec,   cudaEventDisableTiming);
    cudaEventCreateWithFlags(&evEctx,  cudaEventDisableTiming);
    cudaEventCreateWithFlags(&evPgen,  cudaEventDisableTiming);

    // main stream: GRU
    k_grugemm<<<dim3(J3H / 128, B / 16, 2), 256>>>(W_ih, W_hh, tok, emb, lh);
    k_gates<<<4 * B, 128>>>(lh, b_ih, b_hh, w_h, w_d, out);
    cudaEventRecord(evGates, 0);

    // side stream: decoder attention (needs g_hwd from gates)
    cudaStreamWaitEvent(s1, evGates, 0);
    k_dec<<<B, 512, DEC_SMEM, s1>>>(pds, out);
    cudaEventRecord(evDec, s1);

    // main stream: encoder attention chain
    k_attsc<<<(B * S) / 8, 256>>>(enc);
    k_temporal<<<B, 512>>>(pa, out);
    k_ectx<<<dim3(5, B), 512>>>(enc, out);
    cudaEventRecord(evEctx, 0);

    // side stream: p_gen (needs ectx + dctx)
    cudaStreamWaitEvent(s1, evEctx, 0);
    k_pgen<<<16, 256, 0, s1>>>(gen_W, gen_b, ctrl, out);
    cudaEventRecord(evPgen, s1);

    // main stream: output head (needs dctx too)
    cudaStreamWaitEvent(0, evDec, 0);
    k_outh<<<dim3(16, 4), 256>>>(outh_W, outh_b, ctrl);
    cudaStreamWaitEvent(0, evPgen, 0);   // pgen zeros g_sumexp before outv atomics
    k_outv_mma<<<(V + 127) / 128, 512, OUTV_DSMEM>>>(outv_W, outv_b);
    k_pfinal<<<dim3((VP / 4 + 255) / 256, B), 256>>>(out);
    k_scatter<<<B, 512>>>(fiv, out);

    cudaEventDestroy(evGates);
    cudaEventDestroy(evDec);
    cudaEventDestroy(evEctx);
    cudaEventDestroy(evPgen);
    cudaStreamDestroy(s1);
}